// round 15
// baseline (speedup 1.0000x reference)
#include <cuda_runtime.h>

#define NL 14
typedef unsigned long long u64;

struct Params {
    const float* x;
    const float* w[NL];
    const float* b[NL];
    float* out;
    int n;
};

// ALL parameters constant-resident, ROW-pack dup layout:
//   w[woff + j*STRIDE + k] = {w[j,k], w[j,k]}  (stride even -> 16B rows)
//   b[boff + j]            = {b_j, b_j}
struct CPack {
    u64 w[1226];
    u64 b[122];
};
__constant__ CPack cpk;
__device__ CPack d_stage;   // staging, filled by pack kernel, copied to cpk

// ---------- packed f32x2 helpers ----------
__device__ __forceinline__ u64 ffma2(u64 a, u64 b, u64 c) {
    u64 d;
    asm("fma.rn.f32x2 %0, %1, %2, %3;" : "=l"(d) : "l"(a), "l"(b), "l"(c));
    return d;
}
__device__ __forceinline__ u64 fadd2(u64 a, u64 b) {
    u64 d;
    asm("add.rn.f32x2 %0, %1, %2;" : "=l"(d) : "l"(a), "l"(b));
    return d;
}
__device__ __forceinline__ u64 pk(float a, float b) {
    u64 r;
    asm("mov.b64 %0, {%1, %2};" : "=l"(r) : "f"(a), "f"(b));
    return r;
}
__device__ __forceinline__ void upk(u64 v, float& a, float& b) {
    asm("mov.b64 {%0, %1}, %2;" : "=f"(a), "=f"(b) : "l"(v));
}

// ---------- one layer, ROW-packed f32x2 (pair = {row0, row1}) ----------
// Each 16B const load (2 adjacent k dups) feeds 2 FFMA2s. The output array
// IS the skip identity (same representation) — saving it costs nothing
// (regs) or one STS.64 per pair (smem, no conversion).
// SKIP: fold identity into accumulator init with fadd2 (pre-ReLU; same math
// as (Wx+b)+id). SKSTR: 1 = register array, 128 = tid-strided smem.
// SAVESM: additionally store post-ReLU outputs to tid-strided smem.
template<int DIN, int STRIDE, int DOUT, bool RELU, bool SKIP, bool SAVESM, int SKSTR>
__device__ __forceinline__ void layerRP(
    const u64* __restrict__ wt, const u64* __restrict__ bd,
    const u64* in, u64* out, const u64* skip, u64* sm_dst)
{
    constexpr int KP = (DIN + 1) / 2;
#pragma unroll
    for (int j = 0; j < DOUT; ++j) {
        u64 acc = bd[j];
        if constexpr (SKIP) acc = fadd2(acc, skip[j * SKSTR]);
        const ulonglong2* __restrict__ w2 =
            reinterpret_cast<const ulonglong2*>(wt + j * STRIDE);
#pragma unroll
        for (int kp = 0; kp < KP; ++kp) {
            ulonglong2 ww = w2[kp];                 // 16B const load: 2 dup weights
            acc = ffma2(in[2 * kp], ww.x, acc);
            if (2 * kp + 1 < DIN)
                acc = ffma2(in[2 * kp + 1], ww.y, acc);
        }
        u64 res;
        if constexpr (RELU) {
            float u, v;
            upk(acc, u, v);
            res = pk(fmaxf(u, 0.f), fmaxf(v, 0.f));
        } else {
            res = acc;
        }
        out[j] = res;
        if constexpr (SAVESM) sm_dst[j * 128] = res;
    }
}

// Layer geometry tables (for the pack kernel).
__device__ __constant__ int c_din[NL]  = {12,12,11,10,9,8,7,6,7,8,9,10,11,12};
__device__ __constant__ int c_dout[NL] = {12,11,10,9,8,7,6,7,8,9,10,11,12,2};
__device__ __constant__ int c_str[NL]  = {12,12,12,10,10,8,8,6,8,8,10,10,12,12};
__device__ __constant__ int c_woff[NL] = {0,144,276,396,486,566,622,670,712,776,848,948,1058,1202};
__device__ __constant__ int c_boff[NL] = {0,12,23,33,42,50,57,63,70,78,87,97,108,120};

// ---- prep kernel: one block per layer, builds row-pack dup tables ----
__global__ void csnet14_pack_kernel(Params p)
{
    const int L = blockIdx.x;
    const int tid = threadIdx.x;
    const int din = c_din[L], dout = c_dout[L], str = c_str[L];
    const float* __restrict__ w = p.w[L];
    u64* dst = d_stage.w + c_woff[L];
    for (int s = tid; s < dout * str; s += 128) {
        int j = s / str, k = s - j * str;
        float v = (k < din) ? w[j * din + k] : 0.f;
        dst[s] = ((u64)__float_as_uint(v) << 32) | __float_as_uint(v);
    }
    const float* __restrict__ b = p.b[L];
    for (int s = tid; s < dout; s += 128) {
        float bv = b[s];
        d_stage.b[c_boff[L] + s] =
            ((u64)__float_as_uint(bv) << 32) | __float_as_uint(bv);
    }
}

__global__ void __launch_bounds__(128, 4) csnet14_kernel(Params p)
{
    // id1/id2 u64-pair spill, tid-strided, thread-private -> no barriers.
    // slots: id1 0-11, id2 12-22
    __shared__ u64 idsm[23 * 128];         // 23552 B

    const int tid = threadIdx.x;
    const int n = p.n;
    const int pairs = (n + 1) >> 1;
    const int gid = blockIdx.x * 128 + tid;
    if (gid >= pairs) return;

    const int r0 = 2 * gid;
    const int r1 = (r0 + 1 < n) ? r0 + 1 : r0;

    const float4* xa = (const float4*)(p.x + (size_t)r0 * 12);
    const float4* xb = (const float4*)(p.x + (size_t)r1 * 12);
    float4 A0 = xa[0], A1 = xa[1], A2 = xa[2];
    float4 B0 = xb[0], B1 = xb[1], B2 = xb[2];

    // ---- input rows -> row-packed pairs {row0_k, row1_k} ----
    u64 x0[12];
    x0[0]  = pk(A0.x, B0.x); x0[1]  = pk(A0.y, B0.y);
    x0[2]  = pk(A0.z, B0.z); x0[3]  = pk(A0.w, B0.w);
    x0[4]  = pk(A1.x, B1.x); x0[5]  = pk(A1.y, B1.y);
    x0[6]  = pk(A1.z, B1.z); x0[7]  = pk(A1.w, B1.w);
    x0[8]  = pk(A2.x, B2.x); x0[9]  = pk(A2.y, B2.y);
    x0[10] = pk(A2.z, B2.z); x0[11] = pk(A2.w, B2.w);

    // smem id bases (tid-strided, thread-private)
    u64* i1 = idsm +  0 * 128 + tid;
    u64* i2 = idsm + 12 * 128 + tid;

    // activations; a3..a6 double as skip identities (same representation)
    u64 a1[12], a2[11], a3[10], a4[9], a5[8], a6[7], a7[6];
    u64 a8[7], a9[8], a10[9], a11[10], a12[11], a13[12], lg[2];

    const u64* __restrict__ cw = cpk.w;
    const u64* __restrict__ cb = cpk.b;
    u64* const nq = nullptr;

    layerRP<12,12,12,true ,false,true ,1  >(cw+   0, cb+  0, x0,  a1,  nq, i1); // fc1  save->i1
    layerRP<12,12,11,true ,false,true ,1  >(cw+ 144, cb+ 12, a1,  a2,  nq, i2); // fc2  save->i2
    layerRP<11,12,10,true ,false,false,1  >(cw+ 276, cb+ 23, a2,  a3,  nq, nq); // fc3
    layerRP<10,10, 9,true ,false,false,1  >(cw+ 396, cb+ 33, a3,  a4,  nq, nq); // fc4
    layerRP< 9,10, 8,true ,false,false,1  >(cw+ 486, cb+ 42, a4,  a5,  nq, nq); // fc5
    layerRP< 8, 8, 7,true ,false,false,1  >(cw+ 566, cb+ 50, a5,  a6,  nq, nq); // fc6
    layerRP< 7, 8, 6,true ,false,false,1  >(cw+ 622, cb+ 57, a6,  a7,  nq, nq); // fc7
    layerRP< 6, 6, 7,true ,true ,false,1  >(cw+ 670, cb+ 63, a7,  a8,  a6, nq); // fc8  + id6
    layerRP< 7, 8, 8,true ,true ,false,1  >(cw+ 712, cb+ 70, a8,  a9,  a5, nq); // fc9  + id5
    layerRP< 8, 8, 9,true ,true ,false,1  >(cw+ 776, cb+ 78, a9,  a10, a4, nq); // fc10 + id4
    layerRP< 9,10,10,true ,true ,false,1  >(cw+ 848, cb+ 87, a10, a11, a3, nq); // fc11 + id3
    layerRP<10,10,11,true ,true ,false,128>(cw+ 948, cb+ 97, a11, a12, i2, nq); // fc12 + id2 (smem)
    layerRP<11,12,12,true ,true ,false,128>(cw+1058, cb+108, a12, a13, i1, nq); // fc13 + id1 (smem)
    layerRP<12,12, 2,false,false,false,1  >(cw+1202, cb+120, a13, lg,  nq, nq); // fc14 -> logits

    // ---- 2-class softmax as sigmoid, per row ----
    float l0a, l0b, l1a, l1b;
    upk(lg[0], l0a, l0b);   // logit 0 of row0, row1
    upk(lg[1], l1a, l1b);   // logit 1 of row0, row1
    float2 outA, outB;
    {
        float e = __expf(l1a - l0a);
        float inv = __fdividef(1.f, 1.f + e);
        outA = make_float2(inv, e * inv);
    }
    {
        float e = __expf(l1b - l0b);
        float inv = __fdividef(1.f, 1.f + e);
        outB = make_float2(inv, e * inv);
    }

    float2* o = (float2*)p.out;
    o[r0] = outA;
    o[r1] = outB;
}

extern "C" void kernel_launch(void* const* d_in, const int* in_sizes, int n_in,
                              void* d_out, int out_size)
{
    (void)n_in; (void)out_size;
    // Max smem carveout so 4 blocks (23.5KB each) always co-reside.
    cudaFuncSetAttribute(csnet14_kernel,
                         cudaFuncAttributePreferredSharedMemoryCarveout, 100);

    Params p;
    p.x = (const float*)d_in[0];
#pragma unroll
    for (int i = 0; i < NL; ++i) {
        p.w[i] = (const float*)d_in[1 + 2 * i];
        p.b[i] = (const float*)d_in[2 + 2 * i];
    }
    p.out = (float*)d_out;
    p.n = in_sizes[0] / 12;

    // 1) pack row-pack dup tables into staging (14 blocks, one per layer)
    csnet14_pack_kernel<<<NL, 128>>>(p);

    // 2) staging -> constant bank (async D2D copy, graph-capturable)
    void* stage_ptr = nullptr;
    cudaGetSymbolAddress(&stage_ptr, d_stage);
    cudaMemcpyToSymbolAsync(cpk, stage_ptr, sizeof(CPack), 0,
                            cudaMemcpyDeviceToDevice, 0);

    // 3) main kernel
    const int pairs = (p.n + 1) / 2;
    const int blocks = (pairs + 127) / 128;
    csnet14_kernel<<<blocks, 128>>>(p);
}

// round 16
// speedup vs baseline: 1.5130x; 1.5130x over previous
#include <cuda_runtime.h>

#define NL 14
typedef unsigned long long u64;

struct Params {
    const float* x;
    const float* w[NL];
    const float* b[NL];
    float* out;
    int n;
};

// ALL weights + biases constant-resident (uniform-const path, no smem staging).
struct CPack {
    ulonglong2 w[320];
    u64        b[64];
};
__constant__ CPack cpk;
__device__ CPack d_stage;   // staging, filled by pack kernel, copied to cpk

// ---------- packed f32x2 helpers ----------
__device__ __forceinline__ u64 ffma2(u64 a, u64 b, u64 c) {
    u64 d;
    asm("fma.rn.f32x2 %0, %1, %2, %3;" : "=l"(d) : "l"(a), "l"(b), "l"(c));
    return d;
}
__device__ __forceinline__ u64 fadd2(u64 a, u64 b) {
    u64 d;
    asm("add.rn.f32x2 %0, %1, %2;" : "=l"(d) : "l"(a), "l"(b));
    return d;
}
__device__ __forceinline__ u64 pk(float a, float b) {
    u64 r;
    asm("mov.b64 %0, {%1, %2};" : "=l"(r) : "f"(a), "f"(b));
    return r;
}
__device__ __forceinline__ void upk(u64 v, float& a, float& b) {
    asm("mov.b64 {%0, %1}, %2;" : "=f"(a), "=f"(b) : "l"(v));
}

// ---------- one layer, feature-packed f32x2, two rows per thread ----------
// Weights as ulonglong2 per (kp, jp):
//   .x = {w[2jp,2kp],   w[2jp+1,2kp]}   (zero-padded)
//   .y = {w[2jp,2kp+1], w[2jp+1,2kp+1]}
// Activations arrive duplicated: {x_k, x_k}. Odd-DIN pad FFMA2s elided.
// Identities flow as PAIRS {v_2jp, v_2jp+1} (pad half exact 0 by
// construction: pad bias=0, pad weights=0, ReLU(0)=0). SKSTR/IDSTR select
// register (1) or tid-strided smem (128) residency. Skip folds into the
// accumulator init with fadd2 (pre-ReLU, same math as (Wx+b)+id).
// SAVEM: 0 none, 1 scalar regs (logits only), 2 pairs w/ stride IDSTR.
template<int DIN, int DOUT, bool RELU, bool SKIP, int SAVEM, bool WDUP,
         int SKSTR, int IDSTR>
__device__ __forceinline__ void layerFP(
    const ulonglong2* __restrict__ w,
    const u64* __restrict__ bb,
    const u64* dA, const u64* dB,
    u64* oA, u64* oB,
    const u64* skpA, const u64* skpB,      // SKIP pairs (stride SKSTR)
    float* idA, float* idB,                // SAVEM==1
    u64* idpA, u64* idpB)                  // SAVEM==2 (stride IDSTR)
{
    constexpr int KP = (DIN + 1) / 2;
    constexpr int JP = (DOUT + 1) / 2;
    u64 accA[JP], accB[JP];
#pragma unroll
    for (int jp = 0; jp < JP; ++jp) {
        u64 bv = bb[jp];
        if constexpr (SKIP) {
            accA[jp] = fadd2(bv, skpA[jp * SKSTR]);
            accB[jp] = fadd2(bv, skpB[jp * SKSTR]);
        } else {
            accA[jp] = bv;
            accB[jp] = bv;
        }
    }
#pragma unroll
    for (int kp = 0; kp < KP; ++kp) {
        const u64 a0 = dA[2 * kp];
        const u64 b0 = dB[2 * kp];
        u64 a1 = 0, b1 = 0;
        if (2 * kp + 1 < DIN) { a1 = dA[2 * kp + 1]; b1 = dB[2 * kp + 1]; }
#pragma unroll
        for (int jp = 0; jp < JP; ++jp) {
            ulonglong2 ww = w[kp * JP + jp];
            accA[jp] = ffma2(a0, ww.x, accA[jp]);
            accB[jp] = ffma2(b0, ww.x, accB[jp]);
            if (2 * kp + 1 < DIN) {              // compile-time: elide pad FFMA2
                accA[jp] = ffma2(a1, ww.y, accA[jp]);
                accB[jp] = ffma2(b1, ww.y, accB[jp]);
            }
        }
    }
#pragma unroll
    for (int jp = 0; jp < JP; ++jp) {
        float a0, a1, b0, b1;
        upk(accA[jp], a0, a1);
        upk(accB[jp], b0, b1);
        if constexpr (RELU) {
            a0 = fmaxf(a0, 0.f); a1 = fmaxf(a1, 0.f);
            b0 = fmaxf(b0, 0.f); b1 = fmaxf(b1, 0.f);
        }
        if constexpr (SAVEM == 1) {
            idA[2 * jp] = a0; idB[2 * jp] = b0;
            if (2 * jp + 1 < DOUT) { idA[2 * jp + 1] = a1; idB[2 * jp + 1] = b1; }
        }
        if constexpr (SAVEM == 2) {
            idpA[jp * IDSTR] = pk(a0, a1);
            idpB[jp * IDSTR] = pk(b0, b1);
        }
        if constexpr (WDUP) {
            oA[2 * jp] = pk(a0, a0);
            oB[2 * jp] = pk(b0, b0);
            if (2 * jp + 1 < DOUT) {       // consumer elides pad reads for odd DIN
                oA[2 * jp + 1] = pk(a1, a1);
                oB[2 * jp + 1] = pk(b1, b1);
            }
        }
    }
}

// Layer geometry tables (for the pack kernel).
__device__ __constant__ int c_din[NL]  = {12,12,11,10,9,8,7,6,7,8,9,10,11,12};
__device__ __constant__ int c_dout[NL] = {12,11,10,9,8,7,6,7,8,9,10,11,12,2};
__device__ __constant__ int c_woff[NL] = {0,36,72,102,127,147,163,175,187,203,223,248,278,314};
__device__ __constant__ int c_boff[NL] = {0,6,12,17,22,26,30,33,37,41,46,51,57,63};

// ---- prep kernel: one block per layer ----
__global__ void csnet14_pack_kernel(Params p)
{
    const int L = blockIdx.x;
    const int tid = threadIdx.x;
    const int din = c_din[L], dout = c_dout[L];
    const int kp_n = (din + 1) >> 1, jp_n = (dout + 1) >> 1;
    const float* __restrict__ w = p.w[L];
    ulonglong2* dst = d_stage.w + c_woff[L];
    for (int s = tid; s < kp_n * jp_n; s += 128) {
        int kp = s / jp_n, jp = s - kp * jp_n;
        int j0 = 2 * jp, j1 = 2 * jp + 1, k0 = 2 * kp, k1 = 2 * kp + 1;
        float v00 = w[j0 * din + k0];
        float v10 = (j1 < dout) ? w[j1 * din + k0] : 0.f;
        float v01 = (k1 < din) ? w[j0 * din + k1] : 0.f;
        float v11 = (j1 < dout && k1 < din) ? w[j1 * din + k1] : 0.f;
        ulonglong2 e;
        e.x = ((u64)__float_as_uint(v10) << 32) | __float_as_uint(v00);
        e.y = ((u64)__float_as_uint(v11) << 32) | __float_as_uint(v01);
        dst[s] = e;
    }
    const float* __restrict__ b = p.b[L];
    for (int s = tid; s < jp_n; s += 128) {
        float b0 = b[2 * s];
        float b1 = (2 * s + 1 < dout) ? b[2 * s + 1] : 0.f;
        d_stage.b[c_boff[L] + s] =
            ((u64)__float_as_uint(b1) << 32) | __float_as_uint(b0);
    }
}

__global__ void __launch_bounds__(128, 4) csnet14_kernel(Params p)
{
    // id1/id2 pair-form spill only; slots are thread-private (tid-strided),
    // so NO __syncthreads is needed anywhere.
    // slots: id1A 0-5, id1B 6-11, id2A 12-17, id2B 18-23
    __shared__ u64 idsm[24 * 128];         // 24576 B

    const int tid = threadIdx.x;
    const int n = p.n;
    const int pairs = (n + 1) >> 1;
    const int gid = blockIdx.x * 128 + tid;
    if (gid >= pairs) return;

    const int r0 = 2 * gid;
    const int r1 = (r0 + 1 < n) ? r0 + 1 : r0;

    const float4* xa = (const float4*)(p.x + (size_t)r0 * 12);
    const float4* xb = (const float4*)(p.x + (size_t)r1 * 12);
    float4 A0 = xa[0], A1 = xa[1], A2 = xa[2];
    float4 B0 = xb[0], B1 = xb[1], B2 = xb[2];

    // ---- input rows -> duplicated activation u64s ----
    u64 d0A[12], d0B[12];
    d0A[0]=pk(A0.x,A0.x); d0A[1]=pk(A0.y,A0.y); d0A[2]=pk(A0.z,A0.z); d0A[3]=pk(A0.w,A0.w);
    d0A[4]=pk(A1.x,A1.x); d0A[5]=pk(A1.y,A1.y); d0A[6]=pk(A1.z,A1.z); d0A[7]=pk(A1.w,A1.w);
    d0A[8]=pk(A2.x,A2.x); d0A[9]=pk(A2.y,A2.y); d0A[10]=pk(A2.z,A2.z); d0A[11]=pk(A2.w,A2.w);
    d0B[0]=pk(B0.x,B0.x); d0B[1]=pk(B0.y,B0.y); d0B[2]=pk(B0.z,B0.z); d0B[3]=pk(B0.w,B0.w);
    d0B[4]=pk(B1.x,B1.x); d0B[5]=pk(B1.y,B1.y); d0B[6]=pk(B1.z,B1.z); d0B[7]=pk(B1.w,B1.w);
    d0B[8]=pk(B2.x,B2.x); d0B[9]=pk(B2.y,B2.y); d0B[10]=pk(B2.z,B2.z); d0B[11]=pk(B2.w,B2.w);

    // smem id pair bases (tid-strided, thread-private)
    u64* i1A = idsm +  0 * 128 + tid;  u64* i1B = idsm +  6 * 128 + tid;
    u64* i2A = idsm + 12 * 128 + tid;  u64* i2B = idsm + 18 * 128 + tid;

    // register-resident id PAIRS (id3..id6) + dup buffers
    u64 id3A[5], id3B[5], id4A[5], id4B[5];
    u64 id5A[4], id5B[4], id6A[4], id6B[4];
    u64 d1A[12], d1B[12], d2A[12], d2B[12], d3A[10], d3B[10];
    u64 d4A[10], d4B[10], d5A[8],  d5B[8],  d6A[8],  d6B[8];
    u64 d7A[6],  d7B[6],  d8A[8],  d8B[8],  d9A[8],  d9B[8];
    u64 dAA[10], dAB[10], dBA[10], dBB[10], dCA[12], dCB[12], dDA[12], dDB[12];
    float lgA[2], lgB[2];

    const ulonglong2* __restrict__ cw = cpk.w;
    const u64*        __restrict__ cb = cpk.b;
    float* const np = nullptr;
    u64*   const nq = nullptr;

    layerFP<12,12,true ,false,2,true ,1,128>(cw+  0, cb+ 0, d0A,d0B, d1A,d1B, nq,nq, np,np, i1A,i1B);   // fc1  save->i1 (smem)
    layerFP<12,11,true ,false,2,true ,1,128>(cw+ 36, cb+ 6, d1A,d1B, d2A,d2B, nq,nq, np,np, i2A,i2B);   // fc2  save->i2 (smem)
    layerFP<11,10,true ,false,2,true ,1,1  >(cw+ 72, cb+12, d2A,d2B, d3A,d3B, nq,nq, np,np, id3A,id3B); // fc3  save->reg pairs
    layerFP<10, 9,true ,false,2,true ,1,1  >(cw+102, cb+17, d3A,d3B, d4A,d4B, nq,nq, np,np, id4A,id4B); // fc4  save->reg pairs
    layerFP< 9, 8,true ,false,2,true ,1,1  >(cw+127, cb+22, d4A,d4B, d5A,d5B, nq,nq, np,np, id5A,id5B); // fc5  save->reg pairs
    layerFP< 8, 7,true ,false,2,true ,1,1  >(cw+147, cb+26, d5A,d5B, d6A,d6B, nq,nq, np,np, id6A,id6B); // fc6  save->reg pairs
    layerFP< 7, 6,true ,false,0,true ,1,1  >(cw+163, cb+30, d6A,d6B, d7A,d7B, nq,nq, np,np, nq,nq);     // fc7
    layerFP< 6, 7,true ,true ,0,true ,1,1  >(cw+175, cb+33, d7A,d7B, d8A,d8B, id6A,id6B, np,np, nq,nq); // fc8  + id6
    layerFP< 7, 8,true ,true ,0,true ,1,1  >(cw+187, cb+37, d8A,d8B, d9A,d9B, id5A,id5B, np,np, nq,nq); // fc9  + id5
    layerFP< 8, 9,true ,true ,0,true ,1,1  >(cw+203, cb+41, d9A,d9B, dAA,dAB, id4A,id4B, np,np, nq,nq); // fc10 + id4
    layerFP< 9,10,true ,true ,0,true ,1,1  >(cw+223, cb+46, dAA,dAB, dBA,dBB, id3A,id3B, np,np, nq,nq); // fc11 + id3
    layerFP<10,11,true ,true ,0,true ,128,1>(cw+248, cb+51, dBA,dBB, dCA,dCB, i2A,i2B, np,np, nq,nq);   // fc12 + id2 (smem)
    layerFP<11,12,true ,true ,0,true ,128,1>(cw+278, cb+57, dCA,dCB, dDA,dDB, i1A,i1B, np,np, nq,nq);   // fc13 + id1 (smem)
    layerFP<12, 2,false,false,1,false,1,1  >(cw+314, cb+63, dDA,dDB, nq,nq, nq,nq, lgA,lgB, nq,nq);     // fc14 -> logits

    // ---- 2-class softmax as sigmoid, per row ----
    float2 outA, outB;
    {
        float e = __expf(lgA[1] - lgA[0]);
        float inv = __fdividef(1.f, 1.f + e);
        outA = make_float2(inv, e * inv);
    }
    {
        float e = __expf(lgB[1] - lgB[0]);
        float inv = __fdividef(1.f, 1.f + e);
        outB = make_float2(inv, e * inv);
    }

    float2* o = (float2*)p.out;
    o[r0] = outA;
    o[r1] = outB;
}

extern "C" void kernel_launch(void* const* d_in, const int* in_sizes, int n_in,
                              void* d_out, int out_size)
{
    (void)n_in; (void)out_size;
    // Max smem carveout so 4 blocks (24.5KB each) always co-reside.
    cudaFuncSetAttribute(csnet14_kernel,
                         cudaFuncAttributePreferredSharedMemoryCarveout, 100);

    Params p;
    p.x = (const float*)d_in[0];
#pragma unroll
    for (int i = 0; i < NL; ++i) {
        p.w[i] = (const float*)d_in[1 + 2 * i];
        p.b[i] = (const float*)d_in[2 + 2 * i];
    }
    p.out = (float*)d_out;
    p.n = in_sizes[0] / 12;

    // 1) pack all weights+biases into staging (14 blocks, one per layer)
    csnet14_pack_kernel<<<NL, 128>>>(p);

    // 2) staging -> constant bank (async D2D copy, graph-capturable)
    void* stage_ptr = nullptr;
    cudaGetSymbolAddress(&stage_ptr, d_stage);
    cudaMemcpyToSymbolAsync(cpk, stage_ptr, sizeof(CPack), 0,
                            cudaMemcpyDeviceToDevice, 0);

    // 3) main kernel
    const int pairs = (p.n + 1) / 2;
    const int blocks = (pairs + 127) / 128;
    csnet14_kernel<<<blocks, 128>>>(p);
}